// round 1
// baseline (speedup 1.0000x reference)
#include <cuda_runtime.h>

// Problem constants (fixed by setup_inputs)
#define N_FFT   1024
#define HOP     256
#define NBANDS  128
#define T_FR    1001
#define B_SZ    16
#define L_OUT   256000   // (T-1)*HOP
#define PAD     512      // N_FFT/2

// 10-stage radix-2 DIT FFT on 1024 complex points in shared memory.
// Data must already be in bit-reversed order. tw[j] = exp(-2*pi*i*j/1024), j=0..511.
__device__ __forceinline__ void fft1024(float2* a, const float2* tw, int tid)
{
    #pragma unroll
    for (int s = 1; s <= 10; s++) {
        const int half = 1 << (s - 1);
        const int m    = half << 1;
        #pragma unroll
        for (int qq = 0; qq < 2; qq++) {
            int q   = tid + qq * 256;        // butterfly index 0..511
            int grp = q >> (s - 1);
            int pos = q & (half - 1);
            int i1  = grp * m + pos;
            int i2  = i1 + half;
            float2 w = tw[pos << (10 - s)];
            float2 u = a[i1];
            float2 v = a[i2];
            float2 wv = make_float2(w.x * v.x - w.y * v.y,
                                    w.x * v.y + w.y * v.x);
            a[i1] = make_float2(u.x + wv.x, u.y + wv.y);
            a[i2] = make_float2(u.x - wv.x, u.y - wv.y);
        }
        __syncthreads();
    }
}

__global__ __launch_bounds__(256)
void filtered_noise_kernel(const float* __restrict__ fb,     // (B,1,128,T)
                           const float* __restrict__ noise,  // (B,1,L_OUT)
                           float* __restrict__ out)          // (B,1,L_OUT)
{
    __shared__ float2 a[N_FFT];
    __shared__ float2 tw[512];
    __shared__ float  f[NBANDS];

    const int t   = blockIdx.x;
    const int b   = blockIdx.y;
    const int tid = threadIdx.x;

    // Twiddle table: tw[j] = exp(-2*pi*i*j/1024) = (cos(pi*j/512), -sin(pi*j/512))
    #pragma unroll
    for (int j = tid; j < 512; j += 256) {
        float sn, cs;
        sincospif(-(float)j * (1.0f / 512.0f), &sn, &cs);
        tw[j] = make_float2(cs, sn);
    }

    // Filter for this (b, t): 128 band gains (strided gmem loads)
    if (tid < NBANDS)
        f[tid] = fb[(b * NBANDS + tid) * T_FR + t];

    // Load frame samples (scaled 2x-1, zero-padded), stored bit-reversed
    const int base = t * HOP - PAD;   // sample index in un-padded noise coords
    #pragma unroll
    for (int j = tid; j < N_FFT; j += 256) {
        int s = base + j;
        float v = 0.0f;
        if (s >= 0 && s < L_OUT)
            v = noise[b * L_OUT + s] * 2.0f - 1.0f;
        int r = __brev((unsigned)j) >> 22;
        a[r] = make_float2(v, 0.0f);
    }
    __syncthreads();

    // Forward FFT
    fft1024(a, tw, tid);

    // Real filter multiply + conjugate (inverse via conj(fft(conj(X)))/N).
    // Bin 0 -> 0; bin k (1..1023): gain = f[(min(k,1024-k)-1)/4].
    #pragma unroll
    for (int k = tid; k < N_FFT; k += 256) {
        float g = 0.0f;
        if (k != 0) {
            int mk = min(k, N_FFT - k);
            g = f[(mk - 1) >> 2];
        }
        float2 v = a[k];
        a[k] = make_float2(v.x * g, -v.y * g);
    }
    __syncthreads();

    // In-place bit-reversal permutation for the second FFT
    #pragma unroll
    for (int j = tid; j < N_FFT; j += 256) {
        int r = __brev((unsigned)j) >> 22;
        if (r > j) {
            float2 tmp = a[j];
            a[j] = a[r];
            a[r] = tmp;
        }
    }
    __syncthreads();

    // Second FFT; real part / 1024 is the time-domain signal
    fft1024(a, tw, tid);

    // Hann window + overlap-add into the cropped output
    #pragma unroll
    for (int n = tid; n < N_FFT; n += 256) {
        float win = 0.5f * (1.0f - cospif(2.0f * (float)n * (1.0f / 1023.0f)));
        float y = a[n].x * (1.0f / 1024.0f) * win;
        int s = base + n;
        if (s >= 0 && s < L_OUT)
            atomicAdd(&out[b * L_OUT + s], y);
    }
}

extern "C" void kernel_launch(void* const* d_in, const int* in_sizes, int n_in,
                              void* d_out, int out_size)
{
    const float* fb    = (const float*)d_in[0];   // filter_bands (16,1,128,1001)
    const float* noise = (const float*)d_in[1];   // noise (16,1,256000)
    float* out = (float*)d_out;

    cudaMemsetAsync(out, 0, (size_t)out_size * sizeof(float));

    dim3 grid(T_FR, B_SZ);
    filtered_noise_kernel<<<grid, 256>>>(fb, noise, out);
}

// round 2
// speedup vs baseline: 4.8370x; 4.8370x over previous
#include <cuda_runtime.h>

#define N_FFT   1024
#define HOP     256
#define NBANDS  128
#define T_FR    1001
#define B_SZ    16
#define L_OUT   256000
#define PADW    512

// padded smem index: +2 float2 per 16 to kill stride-conflicts on all stage strides
#define PADI(i) ((i) + (((i) >> 4) << 1))

__device__ __forceinline__ float2 cmul(float2 a, float2 b) {
    return make_float2(fmaf(a.x, b.x, -a.y * b.y), fmaf(a.x, b.y, a.y * b.x));
}
__device__ __forceinline__ float2 cadd(float2 a, float2 b){ return make_float2(a.x+b.x, a.y+b.y); }
__device__ __forceinline__ float2 csub(float2 a, float2 b){ return make_float2(a.x-b.x, a.y-b.y); }

// reverse 4 base-4 digits of t (t < 256)
__device__ __forceinline__ int rev4(int t) {
    return ((t & 3) << 6) | ((t & 12) << 2) | ((t >> 2) & 12) | ((t >> 6) & 3);
}

// 5-stage radix-4 DIF forward FFT, N=1024, 256 threads, 4 points/thread.
// Entry: r[m] = x[tid + 256*m] (natural order).
// Exit:  r[m] holds array position 4*tid+m, i.e. bin (256*m + rev4(tid)).
// Caller must sync before the call (tw ready) and before reusing buf after it.
__device__ __forceinline__ void fft1024r4(float2 r[4], float2* buf,
                                          const float2* tw, int tid)
{
    #pragma unroll
    for (int s = 0; s < 5; s++) {
        const int Q = 256 >> (2 * s);
        const int q = tid & (Q - 1);
        float2 t0 = cadd(r[0], r[2]);
        float2 t1 = csub(r[0], r[2]);
        float2 t2 = cadd(r[1], r[3]);
        float2 t3 = make_float2(r[1].y - r[3].y, r[3].x - r[1].x);  // -i*(r1-r3)
        r[0] = cadd(t0, t2);
        r[1] = cadd(t1, t3);
        r[2] = csub(t0, t2);
        r[3] = csub(t1, t3);
        if (s < 4) {
            float2 w1 = tw[q << (2 * s)];
            float2 w2 = cmul(w1, w1);
            float2 w3 = cmul(w2, w1);
            r[1] = cmul(r[1], w1);
            r[2] = cmul(r[2], w2);
            r[3] = cmul(r[3], w3);
            const int base = ((tid >> (8 - 2 * s)) << (10 - 2 * s)) + q;
            #pragma unroll
            for (int m = 0; m < 4; m++)
                buf[PADI(base + m * Q)] = r[m];
            __syncthreads();
            const int s2 = s + 1;
            const int Q2 = 256 >> (2 * s2);
            const int q2 = tid & (Q2 - 1);
            const int base2 = ((tid >> (8 - 2 * s2)) << (10 - 2 * s2)) + q2;
            #pragma unroll
            for (int m = 0; m < 4; m++)
                r[m] = buf[PADI(base2 + m * Q2)];
        }
    }
}

__global__ __launch_bounds__(256)
void filtered_noise_kernel(const float* __restrict__ fb,     // (B,1,128,T)
                           const float* __restrict__ noise,  // (B,1,L_OUT)
                           float* __restrict__ out)          // (B,1,L_OUT)
{
    __shared__ float2 buf[PADI(N_FFT - 1) + 1];   // padded 1024 float2
    __shared__ float2 tw[256];                    // W_1024^j, j=0..255
    __shared__ float  f0[NBANDS], f1[NBANDS];

    const int p   = blockIdx.x;         // frame pair index
    const int b   = blockIdx.y;
    const int tid = threadIdx.x;
    const int t0  = 2 * p;
    const int t1  = t0 + 1;
    const bool v1 = (t1 < T_FR);

    // twiddles: tw[j] = exp(-2*pi*i*j/1024)
    {
        float sn, cs;
        sincospif(-(float)tid * (1.0f / 512.0f), &sn, &cs);
        tw[tid] = make_float2(cs, sn);
    }
    // per-frame band gains
    if (tid < NBANDS) {
        f0[tid] = fb[(b * NBANDS + tid) * T_FR + t0];
        f1[tid] = v1 ? fb[(b * NBANDS + tid) * T_FR + t1] : 0.0f;
    }

    // load two real frames packed as one complex signal (straight gmem->regs)
    const int    base0 = t0 * HOP - PADW;
    const size_t nOff  = (size_t)b * L_OUT;
    float2 r[4];
    #pragma unroll
    for (int m = 0; m < 4; m++) {
        int j  = tid + 256 * m;
        int s0 = base0 + j;
        int s1 = s0 + HOP;
        float a = (s0 >= 0 && s0 < L_OUT) ? fmaf(noise[nOff + s0], 2.0f, -1.0f) : 0.0f;
        float c = (v1 && s1 >= 0 && s1 < L_OUT) ? fmaf(noise[nOff + s1], 2.0f, -1.0f) : 0.0f;
        r[m] = make_float2(a, c);
    }
    __syncthreads();   // tw / f ready

    // forward FFT of z = x0 + i*x1
    fft1024r4(r, buf, tw, tid);

    __syncthreads();   // all stage-4 reads done before buf is overwritten
    const int rv = rev4(tid);
    #pragma unroll
    for (int m = 0; m < 4; m++)
        buf[PADI(256 * m + rv)] = r[m];    // scatter Z to natural bin order
    __syncthreads();

    // spectral unpack + real-filter + repack + conj (input for inverse-as-forward)
    // W[k] = 0.5*(g0+g1)*Z[k] + 0.5*(g0-g1)*conj(Z[N-k]);  r = conj(W)
    #pragma unroll
    for (int m = 0; m < 4; m++) {
        int k = tid + 256 * m;
        float g0 = 0.0f, g1 = 0.0f;
        if (k != 0) {
            int mk   = min(k, N_FFT - k);
            int band = (mk - 1) >> 2;
            g0 = f0[band];
            g1 = f1[band];
        }
        float gp = 0.5f * (g0 + g1);
        float gm = 0.5f * (g0 - g1);
        float2 Zk = buf[PADI(k)];
        float2 Zm = buf[PADI((N_FFT - k) & (N_FFT - 1))];
        float Wx = gp * Zk.x + gm * Zm.x;
        float Wy = gp * Zk.y - gm * Zm.y;
        r[m] = make_float2(Wx, -Wy);
    }
    __syncthreads();   // combine reads done before fft2 writes buf

    // second forward FFT; ifft(W) = conj(fft(conj(W)))/N -> y0=Re/N, y1=-Im/N
    fft1024r4(r, buf, tw, tid);

    __syncthreads();
    #pragma unroll
    for (int m = 0; m < 4; m++)
        buf[PADI(256 * m + rv)] = make_float2(r[m].x, -r[m].y);  // (y0, y1)*1024 at sample n
    __syncthreads();

    // Hann window + overlap-add (coalesced REDG)
    #pragma unroll
    for (int m = 0; m < 4; m++) {
        int n = tid + 256 * m;
        float2 y = buf[PADI(n)];
        float wn = 0.5f * (1.0f - cospif((float)(2 * n) * (1.0f / 1023.0f)))
                 * (1.0f / 1024.0f);
        int s0 = base0 + n;
        if (s0 >= 0 && s0 < L_OUT)
            atomicAdd(&out[nOff + s0], y.x * wn);
        int s1 = s0 + HOP;
        if (v1 && s1 >= 0 && s1 < L_OUT)
            atomicAdd(&out[nOff + s1], y.y * wn);
    }
}

extern "C" void kernel_launch(void* const* d_in, const int* in_sizes, int n_in,
                              void* d_out, int out_size)
{
    const float* fb    = (const float*)d_in[0];   // (16,1,128,1001)
    const float* noise = (const float*)d_in[1];   // (16,1,256000)
    float* out = (float*)d_out;

    cudaMemsetAsync(out, 0, (size_t)out_size * sizeof(float));

    dim3 grid((T_FR + 1) / 2, B_SZ);
    filtered_noise_kernel<<<grid, 256>>>(fb, noise, out);
}

// round 3
// speedup vs baseline: 6.7223x; 1.3898x over previous
#include <cuda_runtime.h>

#define HOP    256
#define NB     128
#define TFR    1001
#define LOUT   256000
#define NPAIR  501            // ceil(1001/2)
#define PADI(i) ((i) + ((i) >> 4))

__device__ __forceinline__ float2 cmul(float2 a, float2 b) {
    return make_float2(fmaf(a.x, b.x, -a.y * b.y), fmaf(a.x, b.y, a.y * b.x));
}
__device__ __forceinline__ float2 cadd(float2 a, float2 b){ return make_float2(a.x+b.x, a.y+b.y); }
__device__ __forceinline__ float2 csub(float2 a, float2 b){ return make_float2(a.x-b.x, a.y-b.y); }

// base-4 digit reversal of a 10-bit index (5 digits)
__device__ __forceinline__ int rev4_10(int x) {
    return ((x & 3) << 8) | ((x & 12) << 4) | (x & 48) | ((x >> 4) & 12) | ((x >> 8) & 3);
}

// DIF radix-4 butterfly, post-twiddles (outputs 1..3 scaled by w1,w1^2,w1^3)
template<bool TW>
__device__ __forceinline__ void bf_dif(float2& a, float2& b, float2& c, float2& d, float2 w1) {
    float2 t0 = cadd(a, c), t1 = csub(a, c), t2 = cadd(b, d);
    float2 t3 = make_float2(b.y - d.y, d.x - b.x);       // -i*(b-d)
    a = cadd(t0, t2);
    float2 o1 = cadd(t1, t3), o2 = csub(t0, t2), o3 = csub(t1, t3);
    if (TW) {
        float2 w2 = cmul(w1, w1), w3 = cmul(w2, w1);
        b = cmul(o1, w1); c = cmul(o2, w2); d = cmul(o3, w3);
    } else { b = o1; c = o2; d = o3; }
}

// DIT radix-4 butterfly, pre-twiddles (inputs 1..3 scaled by w1,w1^2,w1^3)
template<bool TW>
__device__ __forceinline__ void bf_dit(float2& a, float2& b, float2& c, float2& d, float2 w1) {
    if (TW) {
        float2 w2 = cmul(w1, w1), w3 = cmul(w2, w1);
        b = cmul(b, w1); c = cmul(c, w2); d = cmul(d, w3);
    }
    float2 t0 = cadd(a, c), t1 = csub(a, c), t2 = cadd(b, d), t3 = csub(b, d);
    a = cadd(t0, t2);
    c = csub(t0, t2);
    b = make_float2(t1.x + t3.y, t1.y - t3.x);  // t1 - i*t3
    d = make_float2(t1.x - t3.y, t1.y + t3.x);  // t1 + i*t3
}

#define BARS() asm volatile("bar.sync %0, 64;" :: "r"(sub + 1) : "memory")

__global__ __launch_bounds__(128)
void filtered_noise_kernel(const float* __restrict__ fb,     // (16,1,128,1001)
                           const float* __restrict__ noise,  // (16,1,256000)
                           float* __restrict__ out)          // (16,1,256000)
{
    __shared__ float2 bufA[2][PADI(1023) + 1];
    __shared__ float2 bufB[2][PADI(1023) + 1];
    __shared__ float2 tw[256];
    __shared__ float  F[2][2][NB];

    const int tid = threadIdx.x;
    const int sub = tid >> 6;          // 0..1 : independent FFT pipeline
    const int j   = tid & 63;          // lane within pipeline
    const int b   = blockIdx.y;
    const int pr  = blockIdx.x * 2 + sub;   // frame-pair index

    // twiddles: tw[u] = exp(-2*pi*i*u/1024)
    #pragma unroll
    for (int u = tid; u < 256; u += 128) {
        float sn, cs;
        sincospif(-(float)u * (1.0f / 512.0f), &sn, &cs);
        tw[u] = make_float2(cs, sn);
    }
    __syncthreads();
    if (pr >= NPAIR) return;

    const int  t0 = 2 * pr;
    const bool v1 = (t0 + 1) < TFR;

    float* F0 = F[sub][0];
    float* F1 = F[sub][1];
    #pragma unroll
    for (int u = j; u < NB; u += 64) {
        F0[u] = fb[(b * NB + u) * TFR + t0];
        F1[u] = v1 ? fb[(b * NB + u) * TFR + t0 + 1] : 0.0f;
    }

    float2* BA = bufA[sub];
    float2* BB = bufB[sub];
    const int    base0 = t0 * HOP - 512;
    const size_t nOff  = (size_t)b * LOUT;

    // ---- load: layout A, p = j + 64m; z = frame(t0) + i*frame(t1) ----
    float2 r[16];
    #pragma unroll
    for (int m = 0; m < 16; m++) {
        int s0 = base0 + j + 64 * m;
        int s1 = s0 + HOP;
        float xa = (s0 >= 0 && s0 < LOUT) ? fmaf(noise[nOff + s0], 2.0f, -1.0f) : 0.0f;
        float xb = (v1 && s1 >= 0 && s1 < LOUT) ? fmaf(noise[nOff + s1], 2.0f, -1.0f) : 0.0f;
        r[m] = make_float2(xa, xb);
    }

    // ================= forward FFT (DIF, natural -> digit-reversed) =================
    #pragma unroll
    for (int m0 = 0; m0 < 4; m0++)          // stage 0: Q=256, q = j + 64*m0
        bf_dif<true>(r[m0], r[m0 + 4], r[m0 + 8], r[m0 + 12], tw[j + 64 * m0]);
    {
        float2 w1 = tw[j << 2];             // stage 1: Q=64, q = j
        #pragma unroll
        for (int v = 0; v < 4; v++)
            bf_dif<true>(r[4*v], r[4*v + 1], r[4*v + 2], r[4*v + 3], w1);
    }
    // exchange 1: layout A -> layout B
    #pragma unroll
    for (int m = 0; m < 16; m++) BA[PADI(j + 64 * m)] = r[m];
    BARS();
    #pragma unroll
    for (int m = 0; m < 16; m++) r[m] = BA[PADI((j & 3) + 64 * (j >> 2) + 4 * m)];

    #pragma unroll
    for (int m0 = 0; m0 < 4; m0++)          // stage 2: Q=16, q = (j&3) + 4*m0
        bf_dif<true>(r[m0], r[m0 + 4], r[m0 + 8], r[m0 + 12], tw[((j & 3) + 4 * m0) << 4]);
    {
        float2 w1 = tw[(j & 3) << 6];       // stage 3: Q=4, q = j&3
        #pragma unroll
        for (int v = 0; v < 4; v++)
            bf_dif<true>(r[4*v], r[4*v + 1], r[4*v + 2], r[4*v + 3], w1);
    }
    // exchange 2: layout B -> layout C
    #pragma unroll
    for (int m = 0; m < 16; m++) BB[PADI((j & 3) + 64 * (j >> 2) + 4 * m)] = r[m];
    BARS();
    #pragma unroll
    for (int m = 0; m < 16; m++) r[m] = BB[PADI(16 * j + m)];

    {
        float2 dummy = make_float2(1.0f, 0.0f);  // stage 4: Q=1, no twiddle
        #pragma unroll
        for (int v = 0; v < 4; v++)
            bf_dif<false>(r[4*v], r[4*v + 1], r[4*v + 2], r[4*v + 3], dummy);
    }

    // ============ spectral combine in digit-reversed domain ============
    // position p holds bin k = rev4(p); partner (bin N-k) at rev4((1024-k)&1023)
    #pragma unroll
    for (int m = 0; m < 16; m++) BA[PADI(16 * j + m)] = r[m];
    BARS();
    #pragma unroll
    for (int m = 0; m < 16; m++) {
        int p = 16 * j + m;
        int k = rev4_10(p);
        float g0 = 0.0f, g1 = 0.0f;
        if (k != 0) {
            int mk   = min(k, 1024 - k);
            int band = (mk - 1) >> 2;
            g0 = F0[band];
            g1 = F1[band];
        }
        float gp = 0.5f * (g0 + g1);
        float gm = 0.5f * (g0 - g1);
        int pp = rev4_10((1024 - k) & 1023);
        float2 Zk = r[m];
        float2 Zm = BA[PADI(pp)];
        float Wx = gp * Zk.x + gm * Zm.x;
        float Wy = gp * Zk.y - gm * Zm.y;
        r[m] = make_float2(Wx, -Wy);        // conj(W): inverse via forward DIT
    }

    // ================= inverse FFT (DIT, digit-reversed -> natural) =================
    {
        float2 dummy = make_float2(1.0f, 0.0f);  // stage 0: Q=1, q=0
        #pragma unroll
        for (int v = 0; v < 4; v++)
            bf_dit<false>(r[4*v], r[4*v + 1], r[4*v + 2], r[4*v + 3], dummy);
    }
    #pragma unroll
    for (int m0 = 0; m0 < 4; m0++)          // stage 1: Q=4, q = m0
        bf_dit<true>(r[m0], r[m0 + 4], r[m0 + 8], r[m0 + 12], tw[m0 << 6]);

    // exchange 3: layout C -> layout B2 (p = 256*(j>>4) + (j&15) + 16m)
    #pragma unroll
    for (int m = 0; m < 16; m++) BB[PADI(16 * j + m)] = r[m];
    BARS();
    #pragma unroll
    for (int m = 0; m < 16; m++) r[m] = BB[PADI(256 * (j >> 4) + (j & 15) + 16 * m)];

    {
        float2 w1 = tw[(j & 15) << 4];      // stage 2: Q=16, q = j&15
        #pragma unroll
        for (int v = 0; v < 4; v++)
            bf_dit<true>(r[4*v], r[4*v + 1], r[4*v + 2], r[4*v + 3], w1);
    }
    #pragma unroll
    for (int m0 = 0; m0 < 4; m0++)          // stage 3: Q=64, q = (j&15) + 16*m0
        bf_dit<true>(r[m0], r[m0 + 4], r[m0 + 8], r[m0 + 12], tw[((j & 15) + 16 * m0) << 2]);

    // exchange 4: layout B2 -> layout D (p = j + 64m)
    #pragma unroll
    for (int m = 0; m < 16; m++) BA[PADI(256 * (j >> 4) + (j & 15) + 16 * m)] = r[m];
    BARS();
    #pragma unroll
    for (int m = 0; m < 16; m++) r[m] = BA[PADI(j + 64 * m)];

    #pragma unroll
    for (int m0 = 0; m0 < 4; m0++)          // stage 4: Q=256, q = j + 64*m0
        bf_dit<true>(r[m0], r[m0 + 4], r[m0 + 8], r[m0 + 12], tw[j + 64 * m0]);

    // ---- Hann window + overlap-add straight from registers (coalesced) ----
    #pragma unroll
    for (int m = 0; m < 16; m++) {
        int n = j + 64 * m;
        float win = 0.5f * (1.0f - cospif((float)(2 * n) * (1.0f / 1023.0f)))
                  * (1.0f / 1024.0f);
        int s0 = base0 + n;
        if (s0 >= 0 && s0 < LOUT)
            atomicAdd(&out[nOff + s0], r[m].x * win);
        int s1 = s0 + HOP;
        if (v1 && s1 >= 0 && s1 < LOUT)
            atomicAdd(&out[nOff + s1], -r[m].y * win);
    }
}

extern "C" void kernel_launch(void* const* d_in, const int* in_sizes, int n_in,
                              void* d_out, int out_size)
{
    const float* fb    = (const float*)d_in[0];
    const float* noise = (const float*)d_in[1];
    float* out = (float*)d_out;

    cudaMemsetAsync(out, 0, (size_t)out_size * sizeof(float));

    dim3 grid((NPAIR + 1) / 2, 16);
    filtered_noise_kernel<<<grid, 128>>>(fb, noise, out);
}

// round 4
// speedup vs baseline: 8.0384x; 1.1958x over previous
#include <cuda_runtime.h>

#define HOP    256
#define NB     128
#define TFR    1001
#define LOUT   256000
#define NPAIR  501            // ceil(1001/2)
#define PADI(i) ((i) + ((i) >> 4))

// ---- packed f32x2 ops (Blackwell; ptxas never emits these from C++) ----
__device__ __forceinline__ float2 padd(float2 a, float2 b) {
    float2 r;
    asm("add.rn.f32x2 %0, %1, %2;"
        : "=l"(reinterpret_cast<unsigned long long&>(r))
        : "l"(reinterpret_cast<unsigned long long&>(a)),
          "l"(reinterpret_cast<unsigned long long&>(b)));
    return r;
}
__device__ __forceinline__ float2 psub(float2 a, float2 b) {
    float2 r;
    asm("sub.rn.f32x2 %0, %1, %2;"
        : "=l"(reinterpret_cast<unsigned long long&>(r))
        : "l"(reinterpret_cast<unsigned long long&>(a)),
          "l"(reinterpret_cast<unsigned long long&>(b)));
    return r;
}

__device__ __forceinline__ float2 cmul(float2 a, float2 b) {
    return make_float2(fmaf(a.x, b.x, -a.y * b.y), fmaf(a.x, b.y, a.y * b.x));
}

// base-4 digit reversal of a 10-bit index (5 digits)
__device__ __forceinline__ int rev4_10(int x) {
    return ((x & 3) << 8) | ((x & 12) << 4) | (x & 48) | ((x >> 4) & 12) | ((x >> 8) & 3);
}

// DIF radix-4 butterfly, post-twiddles
template<bool TW>
__device__ __forceinline__ void bf_dif(float2& a, float2& b, float2& c, float2& d, float2 w1) {
    float2 t0 = padd(a, c), t1 = psub(a, c), t2 = padd(b, d);
    float2 t3 = make_float2(b.y - d.y, d.x - b.x);       // -i*(b-d)
    a = padd(t0, t2);
    float2 o1 = padd(t1, t3), o2 = psub(t0, t2), o3 = psub(t1, t3);
    if (TW) {
        float2 w2 = cmul(w1, w1), w3 = cmul(w2, w1);
        b = cmul(o1, w1); c = cmul(o2, w2); d = cmul(o3, w3);
    } else { b = o1; c = o2; d = o3; }
}

// DIT radix-4 butterfly, pre-twiddles
template<bool TW>
__device__ __forceinline__ void bf_dit(float2& a, float2& b, float2& c, float2& d, float2 w1) {
    if (TW) {
        float2 w2 = cmul(w1, w1), w3 = cmul(w2, w1);
        b = cmul(b, w1); c = cmul(c, w2); d = cmul(d, w3);
    }
    float2 t0 = padd(a, c), t1 = psub(a, c), t2 = padd(b, d), t3 = psub(b, d);
    a = padd(t0, t2);
    c = psub(t0, t2);
    b = make_float2(t1.x + t3.y, t1.y - t3.x);  // t1 - i*t3
    d = make_float2(t1.x - t3.y, t1.y + t3.x);  // t1 + i*t3
}

#define BARS() asm volatile("bar.sync %0, 64;" :: "r"(sub + 1) : "memory")

__global__ __launch_bounds__(128)
void filtered_noise_kernel(const float* __restrict__ fb,     // (16,1,128,1001)
                           const float* __restrict__ noise,  // (16,1,256000)
                           float* __restrict__ out)          // (16,1,256000)
{
    __shared__ float2 bufA[2][PADI(1023) + 1];
    __shared__ float2 bufB[2][PADI(1023) + 1];
    __shared__ float2 tw[256];
    __shared__ float  F[2][2][NB + 1];          // +sentinel gain 0 at [128]
    __shared__ unsigned int ppt[1024];          // partner index (PADI-ed), transposed [m][j]
    __shared__ float  wint[1024];               // Hann window * (1/1024)

    const int tid = threadIdx.x;
    const int sub = tid >> 6;
    const int j   = tid & 63;
    const int b   = blockIdx.y;
    const int pr  = blockIdx.x * 2 + sub;

    // twiddles: tw[u] = exp(-2*pi*i*u/1024)
    #pragma unroll
    for (int u = tid; u < 256; u += 128) {
        float sn, cs;
        sincospif(-(float)u * (1.0f / 512.0f), &sn, &cs);
        tw[u] = make_float2(cs, sn);
    }
    // partner-index + window tables (shared by both pipelines)
    #pragma unroll
    for (int idx = tid; idx < 1024; idx += 128) {
        int jj = idx & 63, mm = idx >> 6;
        int p  = 16 * jj + mm;
        int k  = rev4_10(p);
        int pp = rev4_10((1024 - k) & 1023);
        ppt[idx] = (unsigned int)PADI(pp);
        wint[idx] = 0.5f * (1.0f - cospif((float)(2 * idx) * (1.0f / 1023.0f)))
                  * (1.0f / 1024.0f);
    }
    __syncthreads();
    if (pr >= NPAIR) return;

    const int  t0 = 2 * pr;
    const bool v1 = (t0 + 1) < TFR;

    float* F0 = F[sub][0];
    float* F1 = F[sub][1];
    #pragma unroll
    for (int u = j; u < NB; u += 64) {
        F0[u] = fb[(b * NB + u) * TFR + t0];
        F1[u] = v1 ? fb[(b * NB + u) * TFR + t0 + 1] : 0.0f;
    }
    if (j == 0) { F0[NB] = 0.0f; F1[NB] = 0.0f; }

    float2* BA = bufA[sub];
    float2* BB = bufB[sub];
    const int    base0 = t0 * HOP - 512;
    const size_t nOff  = (size_t)b * LOUT;
    const bool interior = (base0 >= 0) && (base0 + 1280 <= LOUT);

    // ---- load: layout A, p = j + 64m; z = frame(t0) + i*frame(t1) ----
    float2 r[16];
    if (interior) {
        const float* np = noise + nOff + base0 + j;
        #pragma unroll
        for (int m = 0; m < 16; m++) {
            float xa = np[64 * m];
            float xb = np[64 * m + 256];
            r[m] = make_float2(fmaf(xa, 2.0f, -1.0f), fmaf(xb, 2.0f, -1.0f));
        }
    } else {
        #pragma unroll
        for (int m = 0; m < 16; m++) {
            int s0 = base0 + j + 64 * m;
            int s1 = s0 + HOP;
            float xa = (s0 >= 0 && s0 < LOUT) ? fmaf(noise[nOff + s0], 2.0f, -1.0f) : 0.0f;
            float xb = (v1 && s1 >= 0 && s1 < LOUT) ? fmaf(noise[nOff + s1], 2.0f, -1.0f) : 0.0f;
            r[m] = make_float2(xa, xb);
        }
    }

    // ================= forward FFT (DIF, natural -> digit-reversed) =================
    #pragma unroll
    for (int m0 = 0; m0 < 4; m0++)          // stage 0: Q=256
        bf_dif<true>(r[m0], r[m0 + 4], r[m0 + 8], r[m0 + 12], tw[j + 64 * m0]);
    {
        float2 w1 = tw[j << 2];             // stage 1: Q=64
        #pragma unroll
        for (int v = 0; v < 4; v++)
            bf_dif<true>(r[4*v], r[4*v + 1], r[4*v + 2], r[4*v + 3], w1);
    }
    #pragma unroll
    for (int m = 0; m < 16; m++) BA[PADI(j + 64 * m)] = r[m];
    BARS();
    #pragma unroll
    for (int m = 0; m < 16; m++) r[m] = BA[PADI((j & 3) + 64 * (j >> 2) + 4 * m)];

    #pragma unroll
    for (int m0 = 0; m0 < 4; m0++)          // stage 2: Q=16
        bf_dif<true>(r[m0], r[m0 + 4], r[m0 + 8], r[m0 + 12], tw[((j & 3) + 4 * m0) << 4]);
    {
        float2 w1 = tw[(j & 3) << 6];       // stage 3: Q=4
        #pragma unroll
        for (int v = 0; v < 4; v++)
            bf_dif<true>(r[4*v], r[4*v + 1], r[4*v + 2], r[4*v + 3], w1);
    }
    #pragma unroll
    for (int m = 0; m < 16; m++) BB[PADI((j & 3) + 64 * (j >> 2) + 4 * m)] = r[m];
    BARS();
    #pragma unroll
    for (int m = 0; m < 16; m++) r[m] = BB[17 * j + m];   // PADI(16j+m) = 17j+m

    {
        float2 dummy = make_float2(1.0f, 0.0f);  // stage 4: Q=1
        #pragma unroll
        for (int v = 0; v < 4; v++)
            bf_dif<false>(r[4*v], r[4*v + 1], r[4*v + 2], r[4*v + 3], dummy);
    }

    // ============ spectral combine in digit-reversed domain ============
    #pragma unroll
    for (int m = 0; m < 16; m++) BA[17 * j + m] = r[m];
    BARS();
    const int rj = ((j & 3) << 4) | (j & 12) | (j >> 4);   // rev-j part of bin index
    #pragma unroll
    for (int m = 0; m < 16; m++) {
        const int Cm = ((m & 3) << 8) | ((m >> 2) << 6);
        int k  = Cm + rj;
        int mk = min(k, 1024 - k);
        int band = (mk == 0) ? NB : ((mk - 1) >> 2);
        float g0 = F0[band], g1 = F1[band];
        float gp = 0.5f * (g0 + g1);
        float gm = 0.5f * (g0 - g1);
        float2 Zk = r[m];
        float2 Zm = BA[ppt[(m << 6) | j]];
        float Wx = fmaf(gp, Zk.x,  gm * Zm.x);
        float Wy = fmaf(gp, Zk.y, -gm * Zm.y);
        r[m] = make_float2(Wx, -Wy);        // conj(W): inverse via forward DIT
    }

    // ================= inverse FFT (DIT, digit-reversed -> natural) =================
    {
        float2 dummy = make_float2(1.0f, 0.0f);  // stage 0: Q=1
        #pragma unroll
        for (int v = 0; v < 4; v++)
            bf_dit<false>(r[4*v], r[4*v + 1], r[4*v + 2], r[4*v + 3], dummy);
    }
    #pragma unroll
    for (int m0 = 0; m0 < 4; m0++)          // stage 1: Q=4
        bf_dit<true>(r[m0], r[m0 + 4], r[m0 + 8], r[m0 + 12], tw[m0 << 6]);

    #pragma unroll
    for (int m = 0; m < 16; m++) BB[17 * j + m] = r[m];
    BARS();
    #pragma unroll
    for (int m = 0; m < 16; m++) r[m] = BB[PADI(256 * (j >> 4) + (j & 15) + 16 * m)];

    {
        float2 w1 = tw[(j & 15) << 4];      // stage 2: Q=16
        #pragma unroll
        for (int v = 0; v < 4; v++)
            bf_dit<true>(r[4*v], r[4*v + 1], r[4*v + 2], r[4*v + 3], w1);
    }
    #pragma unroll
    for (int m0 = 0; m0 < 4; m0++)          // stage 3: Q=64
        bf_dit<true>(r[m0], r[m0 + 4], r[m0 + 8], r[m0 + 12], tw[((j & 15) + 16 * m0) << 2]);

    #pragma unroll
    for (int m = 0; m < 16; m++) BA[PADI(256 * (j >> 4) + (j & 15) + 16 * m)] = r[m];
    BARS();
    #pragma unroll
    for (int m = 0; m < 16; m++) r[m] = BA[PADI(j + 64 * m)];

    #pragma unroll
    for (int m0 = 0; m0 < 4; m0++)          // stage 4: Q=256
        bf_dit<true>(r[m0], r[m0 + 4], r[m0 + 8], r[m0 + 12], tw[j + 64 * m0]);

    // ---- Hann window + overlap-add straight from registers ----
    if (interior) {
        float* op = out + nOff + base0 + j;
        #pragma unroll
        for (int m = 0; m < 16; m++) {
            float win = wint[j + 64 * m];
            atomicAdd(&op[64 * m],        r[m].x * win);
            atomicAdd(&op[64 * m + 256], -r[m].y * win);
        }
    } else {
        #pragma unroll
        for (int m = 0; m < 16; m++) {
            int n = j + 64 * m;
            float win = wint[n];
            int s0 = base0 + n;
            if (s0 >= 0 && s0 < LOUT)
                atomicAdd(&out[nOff + s0], r[m].x * win);
            int s1 = s0 + HOP;
            if (v1 && s1 >= 0 && s1 < LOUT)
                atomicAdd(&out[nOff + s1], -r[m].y * win);
        }
    }
}

extern "C" void kernel_launch(void* const* d_in, const int* in_sizes, int n_in,
                              void* d_out, int out_size)
{
    const float* fb    = (const float*)d_in[0];
    const float* noise = (const float*)d_in[1];
    float* out = (float*)d_out;

    cudaMemsetAsync(out, 0, (size_t)out_size * sizeof(float));

    dim3 grid((NPAIR + 1) / 2, 16);
    filtered_noise_kernel<<<grid, 128>>>(fb, noise, out);
}

// round 5
// speedup vs baseline: 8.9525x; 1.1137x over previous
#include <cuda_runtime.h>

#define HOP    256
#define NB     128
#define TFR    1001
#define LOUT   256000
#define NPAIR  501            // ceil(1001/2)
#define PADI(i) ((i) + ((i) >> 4))

// ---- packed f32x2 ops (Blackwell) ----
__device__ __forceinline__ float2 padd(float2 a, float2 b) {
    float2 r;
    asm("add.rn.f32x2 %0, %1, %2;"
        : "=l"(reinterpret_cast<unsigned long long&>(r))
        : "l"(reinterpret_cast<unsigned long long&>(a)),
          "l"(reinterpret_cast<unsigned long long&>(b)));
    return r;
}
__device__ __forceinline__ float2 psub(float2 a, float2 b) {
    float2 r;
    asm("sub.rn.f32x2 %0, %1, %2;"
        : "=l"(reinterpret_cast<unsigned long long&>(r))
        : "l"(reinterpret_cast<unsigned long long&>(a)),
          "l"(reinterpret_cast<unsigned long long&>(b)));
    return r;
}
__device__ __forceinline__ float2 cmul(float2 a, float2 b) {
    return make_float2(fmaf(a.x, b.x, -a.y * b.y), fmaf(a.x, b.y, a.y * b.x));
}

// 4-digit base-4 reversal of an 8-bit value
__device__ __forceinline__ int rev8(int x) {
    return ((x & 3) << 6) | ((x & 12) << 2) | ((x >> 2) & 12) | ((x >> 6) & 3);
}

// DIF radix-4 butterfly, post-twiddles
template<bool TW>
__device__ __forceinline__ void bf_dif(float2& a, float2& b, float2& c, float2& d, float2 w1) {
    float2 t0 = padd(a, c), t1 = psub(a, c), t2 = padd(b, d);
    float2 t3 = make_float2(b.y - d.y, d.x - b.x);       // -i*(b-d)
    a = padd(t0, t2);
    float2 o1 = padd(t1, t3), o2 = psub(t0, t2), o3 = psub(t1, t3);
    if (TW) {
        float2 w2 = cmul(w1, w1), w3 = cmul(w2, w1);
        b = cmul(o1, w1); c = cmul(o2, w2); d = cmul(o3, w3);
    } else { b = o1; c = o2; d = o3; }
}

// DIT radix-4 butterfly, pre-twiddles
template<bool TW>
__device__ __forceinline__ void bf_dit(float2& a, float2& b, float2& c, float2& d, float2 w1) {
    if (TW) {
        float2 w2 = cmul(w1, w1), w3 = cmul(w2, w1);
        b = cmul(b, w1); c = cmul(c, w2); d = cmul(d, w3);
    }
    float2 t0 = padd(a, c), t1 = psub(a, c), t2 = padd(b, d), t3 = psub(b, d);
    a = padd(t0, t2);
    c = psub(t0, t2);
    b = make_float2(t1.x + t3.y, t1.y - t3.x);  // t1 - i*t3
    d = make_float2(t1.x - t3.y, t1.y + t3.x);  // t1 + i*t3
}

// W[k] = gp*Zk + gm*conj(Zm); returns conj(W)
__device__ __forceinline__ float2 combW(float g0, float g1, float2 Zk, float2 Zm) {
    float gp = 0.5f * (g0 + g1), gm = 0.5f * (g0 - g1);
    return make_float2(fmaf(gp, Zk.x, gm * Zm.x),
                       fmaf(-gp, Zk.y, gm * Zm.y));
}

// register-local spectral combine for quad pair (kappa, 256-kappa), kappa in [1,127]
__device__ __forceinline__ void combine_pair(float2* ra, float2* rb, int kappa,
                                             const float* F0, const float* F1)
{
    float2 a0 = ra[0], a1 = ra[1], a2 = ra[2], a3 = ra[3];
    float2 b0 = rb[0], b1 = rb[1], b2 = rb[2], b3 = rb[3];
    int band0 = (kappa - 1) >> 2;        // mk = kappa
    int band1 = (255 + kappa) >> 2;      // mk = 256+kappa
    int band2 = (511 - kappa) >> 2;      // mk = 512-kappa
    int band3 = (255 - kappa) >> 2;      // mk = 256-kappa
    float g00 = F0[band0], g10 = F1[band0];
    float g01 = F0[band1], g11 = F1[band1];
    float g02 = F0[band2], g12 = F1[band2];
    float g03 = F0[band3], g13 = F1[band3];
    ra[0] = combW(g00, g10, a0, b3);
    ra[1] = combW(g01, g11, a1, b2);
    ra[2] = combW(g02, g12, a2, b1);
    ra[3] = combW(g03, g13, a3, b0);
    rb[0] = combW(g03, g13, b0, a3);
    rb[1] = combW(g02, g12, b1, a2);
    rb[2] = combW(g01, g11, b2, a1);
    rb[3] = combW(g00, g10, b3, a0);
}

#define BARS() asm volatile("bar.sync %0, 64;" :: "r"(sub + 1) : "memory")

__global__ __launch_bounds__(128)
void filtered_noise_kernel(const float* __restrict__ fb,     // (16,1,128,1001)
                           const float* __restrict__ noise,  // (16,1,256000)
                           float* __restrict__ out)          // (16,1,256000)
{
    __shared__ float2 bufA[2][PADI(1023) + 1];
    __shared__ float2 bufB[2][PADI(1023) + 1];
    __shared__ float2 tw[256];
    __shared__ float  F[2][2][NB];
    __shared__ float  wint[1024];       // Hann * (1/1024)

    const int tid = threadIdx.x;
    const int sub = tid >> 6;
    const int j   = tid & 63;
    const int b   = blockIdx.y;
    const int pr  = blockIdx.x * 2 + sub;

    #pragma unroll
    for (int u = tid; u < 256; u += 128) {
        float sn, cs;
        sincospif(-(float)u * (1.0f / 512.0f), &sn, &cs);
        tw[u] = make_float2(cs, sn);
    }
    #pragma unroll
    for (int idx = tid; idx < 1024; idx += 128)
        wint[idx] = 0.5f * (1.0f - cospif((float)(2 * idx) * (1.0f / 1023.0f)))
                  * (1.0f / 1024.0f);
    __syncthreads();
    if (pr >= NPAIR) return;

    const int  t0 = 2 * pr;
    const bool v1 = (t0 + 1) < TFR;

    float* F0 = F[sub][0];
    float* F1 = F[sub][1];
    #pragma unroll
    for (int u = j; u < NB; u += 64) {
        F0[u] = fb[(b * NB + u) * TFR + t0];
        F1[u] = v1 ? fb[(b * NB + u) * TFR + t0 + 1] : 0.0f;
    }

    float2* BA = bufA[sub];
    float2* BB = bufB[sub];
    const int    base0 = t0 * HOP - 512;
    const size_t nOff  = (size_t)b * LOUT;
    const bool interior = (base0 >= 0) && (base0 + 1280 <= LOUT);

    // ---- load: layout A, p = j + 64m; z = frame(t0) + i*frame(t1) ----
    float2 r[16];
    if (interior) {
        const float* np = noise + nOff + base0 + j;
        #pragma unroll
        for (int m = 0; m < 16; m++) {
            float xa = np[64 * m];
            float xb = np[64 * m + 256];
            r[m] = make_float2(fmaf(xa, 2.0f, -1.0f), fmaf(xb, 2.0f, -1.0f));
        }
    } else {
        #pragma unroll
        for (int m = 0; m < 16; m++) {
            int s0 = base0 + j + 64 * m;
            int s1 = s0 + HOP;
            float xa = (s0 >= 0 && s0 < LOUT) ? fmaf(noise[nOff + s0], 2.0f, -1.0f) : 0.0f;
            float xb = (v1 && s1 >= 0 && s1 < LOUT) ? fmaf(noise[nOff + s1], 2.0f, -1.0f) : 0.0f;
            r[m] = make_float2(xa, xb);
        }
    }

    // ================= forward FFT (DIF) =================
    #pragma unroll
    for (int m0 = 0; m0 < 4; m0++)          // stage 0: Q=256
        bf_dif<true>(r[m0], r[m0 + 4], r[m0 + 8], r[m0 + 12], tw[j + 64 * m0]);
    {
        float2 w1 = tw[j << 2];             // stage 1: Q=64
        #pragma unroll
        for (int v = 0; v < 4; v++)
            bf_dif<true>(r[4*v], r[4*v + 1], r[4*v + 2], r[4*v + 3], w1);
    }
    #pragma unroll
    for (int m = 0; m < 16; m++) BA[PADI(j + 64 * m)] = r[m];
    BARS();
    #pragma unroll
    for (int m = 0; m < 16; m++) r[m] = BA[PADI((j & 3) + 64 * (j >> 2) + 4 * m)];

    #pragma unroll
    for (int m0 = 0; m0 < 4; m0++)          // stage 2: Q=16
        bf_dif<true>(r[m0], r[m0 + 4], r[m0 + 8], r[m0 + 12], tw[((j & 3) + 4 * m0) << 4]);
    {
        float2 w1 = tw[(j & 3) << 6];       // stage 3: Q=4
        #pragma unroll
        for (int v = 0; v < 4; v++)
            bf_dif<true>(r[4*v], r[4*v + 1], r[4*v + 2], r[4*v + 3], w1);
    }
    #pragma unroll
    for (int m = 0; m < 16; m++) BB[PADI((j & 3) + 64 * (j >> 2) + 4 * m)] = r[m];
    BARS();

    // ---- paired-quad gather: thread gets quad pairs (ka,256-ka), (kb,255-2j) ----
    const int ka  = 2 * j;
    const int kaS = (j == 0) ? 128 : 256 - 2 * j;
    const int kb  = 2 * j + 1;
    const int kbS = 255 - 2 * j;
    int adr[4];
    {
        int q0 = rev8(ka), q1 = rev8(kaS), q2 = rev8(kb), q3 = rev8(kbS);
        adr[0] = 4 * q0 + (q0 >> 2);
        adr[1] = 4 * q1 + (q1 >> 2);
        adr[2] = 4 * q2 + (q2 >> 2);
        adr[3] = 4 * q3 + (q3 >> 2);
    }
    #pragma unroll
    for (int v = 0; v < 4; v++)
        #pragma unroll
        for (int e = 0; e < 4; e++)
            r[4 * v + e] = BB[adr[v] + e];

    {
        float2 dummy = make_float2(1.0f, 0.0f);  // stage 4: Q=1 (per quad)
        #pragma unroll
        for (int v = 0; v < 4; v++)
            bf_dif<false>(r[4*v], r[4*v + 1], r[4*v + 2], r[4*v + 3], dummy);
    }

    // ---- register-local spectral combine ----
    if (j == 0) {
        // quad kappa=0: bins {0,256,512,768}; DC -> 0; 256<->768; 512 self
        float2 a1 = r[1], a2 = r[2], a3 = r[3];
        float g0a = F0[63],  g1a = F1[63];   // band of mk=256
        float g0b = F0[127], g1b = F1[127];  // band of mk=512
        r[0] = make_float2(0.0f, 0.0f);
        r[1] = combW(g0a, g1a, a1, a3);
        r[2] = combW(g0b, g1b, a2, a2);
        r[3] = combW(g0a, g1a, a3, a1);
        // quad kappa=128 (self-paired): bands {31,95,95,31}, partner 3-e
        float2 b0 = r[4], b1 = r[5], b2 = r[6], b3 = r[7];
        float g0c = F0[31], g1c = F1[31];
        float g0d = F0[95], g1d = F1[95];
        r[4] = combW(g0c, g1c, b0, b3);
        r[5] = combW(g0d, g1d, b1, b2);
        r[6] = combW(g0d, g1d, b2, b1);
        r[7] = combW(g0c, g1c, b3, b0);
    } else {
        combine_pair(r, r + 4, ka, F0, F1);
    }
    combine_pair(r + 8, r + 12, kb, F0, F1);

    // ================= inverse FFT (DIT) =================
    {
        float2 dummy = make_float2(1.0f, 0.0f);  // stage 0: per quad, no twiddle
        #pragma unroll
        for (int v = 0; v < 4; v++)
            bf_dit<false>(r[4*v], r[4*v + 1], r[4*v + 2], r[4*v + 3], dummy);
    }
    // scatter quads back, then load layout p = 64*(j>>2) + (j&3) + 4t
    #pragma unroll
    for (int v = 0; v < 4; v++)
        #pragma unroll
        for (int e = 0; e < 4; e++)
            BA[adr[v] + e] = r[4 * v + e];
    BARS();
    {
        const int base = 68 * (j >> 2) + (j & 3);
        #pragma unroll
        for (int t = 0; t < 16; t++)
            r[t] = BA[base + 4 * t + (t >> 2)];
    }
    {
        float2 w1 = tw[(j & 3) << 6];       // stage 1: q = p&3 = j&3
        #pragma unroll
        for (int h = 0; h < 4; h++)
            bf_dit<true>(r[4*h], r[4*h + 1], r[4*h + 2], r[4*h + 3], w1);
    }
    #pragma unroll
    for (int i = 0; i < 4; i++)             // stage 2: q = (j&3) + 4i
        bf_dit<true>(r[i], r[i + 4], r[i + 8], r[i + 12], tw[((j & 3) + 4 * i) << 4]);

    {
        const int base = 68 * (j >> 2) + (j & 3);
        #pragma unroll
        for (int t = 0; t < 16; t++)
            BB[base + 4 * t + (t >> 2)] = r[t];
    }
    BARS();
    #pragma unroll
    for (int m = 0; m < 16; m++)
        r[m] = BB[PADI(j + 64 * m)];

    {
        float2 w1 = tw[j << 2];             // stage 3: q = j
        #pragma unroll
        for (int v = 0; v < 4; v++)
            bf_dit<true>(r[4*v], r[4*v + 1], r[4*v + 2], r[4*v + 3], w1);
    }
    #pragma unroll
    for (int i = 0; i < 4; i++)             // stage 4: q = j + 64i
        bf_dit<true>(r[i], r[i + 4], r[i + 8], r[i + 12], tw[j + 64 * i]);

    // ---- Hann window + overlap-add straight from registers ----
    if (interior) {
        float* op = out + nOff + base0 + j;
        #pragma unroll
        for (int m = 0; m < 16; m++) {
            float win = wint[j + 64 * m];
            atomicAdd(&op[64 * m],        r[m].x * win);
            atomicAdd(&op[64 * m + 256], -r[m].y * win);
        }
    } else {
        #pragma unroll
        for (int m = 0; m < 16; m++) {
            int n = j + 64 * m;
            float win = wint[n];
            int s0 = base0 + n;
            if (s0 >= 0 && s0 < LOUT)
                atomicAdd(&out[nOff + s0], r[m].x * win);
            int s1 = s0 + HOP;
            if (v1 && s1 >= 0 && s1 < LOUT)
                atomicAdd(&out[nOff + s1], -r[m].y * win);
        }
    }
}

extern "C" void kernel_launch(void* const* d_in, const int* in_sizes, int n_in,
                              void* d_out, int out_size)
{
    const float* fb    = (const float*)d_in[0];
    const float* noise = (const float*)d_in[1];
    float* out = (float*)d_out;

    cudaMemsetAsync(out, 0, (size_t)out_size * sizeof(float));

    dim3 grid((NPAIR + 1) / 2, 16);
    filtered_noise_kernel<<<grid, 128>>>(fb, noise, out);
}